// round 16
// baseline (speedup 1.0000x reference)
#include <cuda_runtime.h>
#include <cstdint>

#define NN    200000
#define DIM   20
#define EE    6400000
#define ITERS 3
#define NBLK  ((NN + 255) / 256)   // 782 scan blocks
#define LIFE_DROP 255

typedef unsigned long long ull;

// Persistent scratch (allocations banned; __device__ globals are the workaround)
__device__ __align__(16) float g_h[(size_t)NN * DIM];
__device__ __align__(16) float g_x[(size_t)NN * DIM];
__device__ unsigned char g_depth8[NN];
// Weight image: [m*200 + k*10 + jp] = (W_m[2jp][k], W_m[2jp+1][k]),
// m in {Wz,Uz,Wr,Ur,Wh,Uh}; biases combined W+U at [1200 + g*10 + jp], g=z,r,h.
__device__ __align__(16) float2 g_stage[1232];
// CSR-by-dst with life classes: A = alive all 3 iters, B = iters 0-1, C = iter 0
__device__ int g_degA[NN];
__device__ int g_degB[NN];
__device__ int g_degC[NN];
// per-node packed CSR metadata: {off, endA, endB, offNext}
__device__ __align__(16) int4 g_meta[NN];
__device__ int g_bsum[1024];
__device__ int g_scan_done;
__device__ __align__(4) unsigned char g_elife[EE];
__device__ __align__(8) unsigned short g_erank[EE];   // rank within (dst,class)
__device__ int g_csr[EE];

// ---------------------------------------------------------------------------
// packed f32x2 helpers
// ---------------------------------------------------------------------------
#define FMA2(d, a, b, c) \
    asm("fma.rn.f32x2 %0, %1, %2, %3;" : "=l"(d) : "l"(a), "l"(b), "l"(c))
#define PACK2(d, lo, hi) \
    asm("mov.b64 %0, {%1, %2};" : "=l"(d) : "f"(lo), "f"(hi))
#define UNPACK2(lo, hi, s) \
    asm("mov.b64 {%0, %1}, %2;" : "=f"(lo), "=f"(hi) : "l"(s))

__device__ __forceinline__ float fsigmoid(float v) {
    return 1.f / (1.f + __expf(-v));
}
__device__ __forceinline__ float ftanh(float x) {
    return fmaf(2.f, 1.f / (1.f + __expf(-2.f * x)), -1.f);
}

// ---------------------------------------------------------------------------
// prep (fused init): copy h, pack depth, zero counters, pack weights/biases
// ---------------------------------------------------------------------------
struct WParams {
    const float* W[6];   // Wz, Uz, Wr, Ur, Wh, Uh   ([DIM,DIM], row = out)
    const float* B[6];   // bz, buz, br, bur, bh, buh
};

__global__ void prep_kernel(const float* __restrict__ h_in,
                            const int* __restrict__ depth, WParams p) {
    int i = blockIdx.x * blockDim.x + threadIdx.x;
    const int n4 = NN * DIM / 4;
    if (i == 0) g_scan_done = 0;
    if (i < n4)
        reinterpret_cast<float4*>(g_h)[i] = reinterpret_cast<const float4*>(h_in)[i];
    if (i < NN) {
        g_depth8[i] = (unsigned char)__ldg(depth + i);
        g_degA[i] = 0; g_degB[i] = 0; g_degC[i] = 0;
    }
    if (i < 1200) {
        int m = i / 200, r = i % 200;
        int k = r / 10, jp = r % 10;
        const float* w = p.W[m];
        g_stage[m * 200 + k * 10 + jp] =
            make_float2(w[(2 * jp) * DIM + k], w[(2 * jp + 1) * DIM + k]);
    } else if (i < 1230) {
        int t = i - 1200;
        int g = t / 10, jp = t % 10;
        const float* b0 = p.B[2 * g];
        const float* b1 = p.B[2 * g + 1];
        g_stage[1200 + g * 10 + jp] =
            make_float2(b0[2 * jp] + b1[2 * jp], b0[2 * jp + 1] + b1[2 * jp + 1]);
    } else if (i < 1232) {
        g_stage[i] = make_float2(0.f, 0.f);
    }
}

// ---------------------------------------------------------------------------
// CSR build: hist (atomics, records rank) -> fused scan -> atomic-free fill
// ---------------------------------------------------------------------------
__global__ void hist_kernel(const int4* __restrict__ esrc4,
                            const int4* __restrict__ edst4) {
    int t = blockIdx.x * blockDim.x + threadIdx.x;
    if (t >= EE / 4) return;
    int4 s4 = __ldg(esrc4 + t);
    int4 d4 = __ldg(edst4 + t);
    int ss[4] = { s4.x, s4.y, s4.z, s4.w };
    int dd[4] = { d4.x, d4.y, d4.z, d4.w };
    unsigned char lf[4];
    unsigned short rk[4];
#pragma unroll
    for (int k = 0; k < 4; k++) {
        int maxd = max((int)g_depth8[ss[k]], (int)g_depth8[dd[k]]);
        unsigned char life = LIFE_DROP;
        int rank = 0;
        if (maxd <= 3) {
            life = (unsigned char)(3 - maxd);
            if (life >= 2)      rank = atomicAdd(&g_degA[dd[k]], 1);
            else if (life == 1) rank = atomicAdd(&g_degB[dd[k]], 1);
            else                rank = atomicAdd(&g_degC[dd[k]], 1);
        }
        lf[k] = life;
        rk[k] = (unsigned short)rank;
    }
    reinterpret_cast<uchar4*>(g_elife)[t] = make_uchar4(lf[0], lf[1], lf[2], lf[3]);
    reinterpret_cast<ushort4*>(g_erank)[t] = make_ushort4(rk[0], rk[1], rk[2], rk[3]);
}

// Single-kernel scan: one wave (782 blocks), software grid barrier.
// Produces packed per-node metadata {off, endA, endB, offNext}.
__global__ void __launch_bounds__(256) scan_kernel() {
    __shared__ int sm[256];
    int b = blockIdx.x;
    int i = b * 256 + threadIdx.x;

    int a = 0, bb = 0, c = 0;
    if (i < NN) { a = g_degA[i]; bb = g_degB[i]; c = g_degC[i]; }
    int v = a + bb + c;

    sm[threadIdx.x] = v;
    __syncthreads();
    for (int off = 1; off < 256; off <<= 1) {
        int add = (threadIdx.x >= off) ? sm[threadIdx.x - off] : 0;
        __syncthreads();
        sm[threadIdx.x] += add;
        __syncthreads();
    }
    int incl = sm[threadIdx.x];
    int btot = sm[255];

    if (threadIdx.x == 0) {
        g_bsum[b] = btot;
        __threadfence();
        atomicAdd(&g_scan_done, 1);
        while (atomicAdd(&g_scan_done, 0) < (int)gridDim.x) { }
    }
    __syncthreads();

    int part = 0;
    for (int t = threadIdx.x; t < b; t += 256) part += g_bsum[t];
    sm[threadIdx.x] = part;
    __syncthreads();
    for (int off = 128; off > 0; off >>= 1) {
        if (threadIdx.x < off) sm[threadIdx.x] += sm[threadIdx.x + off];
        __syncthreads();
    }
    int base = sm[0];

    if (i < NN) {
        int pos = base + incl - v;
        g_meta[i] = make_int4(pos, pos + a, pos + a + bb, pos + v);
    }
}

// fill: atomic-free. pos = class_base(meta) + rank.
__global__ void fill_kernel(const int4* __restrict__ esrc4,
                            const int4* __restrict__ edst4) {
    int t = blockIdx.x * blockDim.x + threadIdx.x;
    if (t >= EE / 4) return;
    uchar4 l4 = reinterpret_cast<const uchar4*>(g_elife)[t];
    ushort4 r4 = reinterpret_cast<const ushort4*>(g_erank)[t];
    unsigned char lf[4] = { l4.x, l4.y, l4.z, l4.w };
    unsigned short rk[4] = { r4.x, r4.y, r4.z, r4.w };
    int4 s4 = __ldg(esrc4 + t);
    int4 d4 = __ldg(edst4 + t);
    int ss[4] = { s4.x, s4.y, s4.z, s4.w };
    int dd[4] = { d4.x, d4.y, d4.z, d4.w };
#pragma unroll
    for (int k = 0; k < 4; k++) {
        unsigned char life = lf[k];
        if (life == LIFE_DROP) continue;
        int4 m = g_meta[dd[k]];
        int base = (life >= 2) ? m.x : (life == 1) ? m.y : m.z;
        g_csr[base + rk[k]] = ss[k];
    }
}

// ---------------------------------------------------------------------------
// gather: x[u] = sum of h[src] over class prefix for this iteration
// ---------------------------------------------------------------------------
__global__ void gather_kernel(int iter, int thr) {
    int lane = threadIdx.x & 31;
    if (lane >= 30) return;                        // 6 groups of 5 per warp
    int warp = (blockIdx.x * blockDim.x + threadIdx.x) >> 5;
    int u = warp * 6 + lane / 5;
    if (u >= NN) return;
    if (g_depth8[u] > thr) return;
    int c = lane % 5;

    int4 m = g_meta[u];
    int beg = m.x;
    int end = (iter == 0) ? m.w : (iter == 1) ? m.z : m.y;

    float4 acc = make_float4(0.f, 0.f, 0.f, 0.f);
    int e = beg;
    for (; e + 4 <= end; e += 4) {
        int s0 = g_csr[e];
        int s1 = g_csr[e + 1];
        int s2 = g_csr[e + 2];
        int s3 = g_csr[e + 3];
        float4 v0 = __ldg(reinterpret_cast<const float4*>(g_h + (size_t)s0 * DIM) + c);
        float4 v1 = __ldg(reinterpret_cast<const float4*>(g_h + (size_t)s1 * DIM) + c);
        float4 v2 = __ldg(reinterpret_cast<const float4*>(g_h + (size_t)s2 * DIM) + c);
        float4 v3 = __ldg(reinterpret_cast<const float4*>(g_h + (size_t)s3 * DIM) + c);
        acc.x += (v0.x + v1.x) + (v2.x + v3.x);
        acc.y += (v0.y + v1.y) + (v2.y + v3.y);
        acc.z += (v0.z + v1.z) + (v2.z + v3.z);
        acc.w += (v0.w + v1.w) + (v2.w + v3.w);
    }
    for (; e < end; e++) {
        int s0 = g_csr[e];
        float4 v0 = __ldg(reinterpret_cast<const float4*>(g_h + (size_t)s0 * DIM) + c);
        acc.x += v0.x; acc.y += v0.y; acc.z += v0.z; acc.w += v0.w;
    }
    reinterpret_cast<float4*>(g_x + (size_t)u * DIM)[c] = acc;
}

// ---------------------------------------------------------------------------
// GRU update: 2 threads per node, register-diet; launch_bounds(256,4).
// Thread `half` owns pair indices jp in [5*half, 5*half+5)
// -> outputs [10*half, 10*half+10).
// ---------------------------------------------------------------------------
__global__ void __launch_bounds__(256, 4) gru_kernel(int thr,
                                                     float* __restrict__ out_final) {
    // ull offsets: Wz=0, Uz=200, Wr=400, Ur=600, Wh=800, Uh=1000,
    //              Bz=1200, Br=1210, Bh=1220 (each + 5*half + jp)
    __shared__ __align__(16) ull sW[1232];
    {
        const float4* src = reinterpret_cast<const float4*>(g_stage);
        float4* dst = reinterpret_cast<float4*>(sW);
        for (int t = threadIdx.x; t < 616; t += blockDim.x)
            dst[t] = src[t];
    }
    __syncthreads();

    int gid  = blockIdx.x * blockDim.x + threadIdx.x;
    int u    = gid >> 1;
    int half = gid & 1;
    bool inb = (u < NN);
    bool act = inb && (g_depth8[u] <= thr);
    unsigned mask = __ballot_sync(0xFFFFFFFFu, act);

    if (!act) {
        if (inb && out_final) {
            float2* o = reinterpret_cast<float2*>(out_final + (size_t)u * DIM + 10 * half);
            float2 z2 = make_float2(0.f, 0.f);
#pragma unroll
            for (int k = 0; k < 5; k++) o[k] = z2;
        }
        return;
    }

    const int base5 = half * 5;
    const bool lowhalf = (half == 0);

    ull accz[5], accr[5], acch[5];
#pragma unroll
    for (int jp = 0; jp < 5; jp++) {
        accz[jp] = sW[1200 + base5 + jp];
        accr[jp] = sW[1210 + base5 + jp];
        acch[jp] = sW[1220 + base5 + jp];
    }

    // ---- Phase A: x contributions (Wz, Wr, Wh); x consumed in chunks ----
    {
        const float4* xp = reinterpret_cast<const float4*>(g_x + (size_t)u * DIM);
#pragma unroll
        for (int c4 = 0; c4 < 5; c4++) {
            float4 a = xp[c4];
            float vals[4] = { a.x, a.y, a.z, a.w };
#pragma unroll
            for (int t = 0; t < 4; t++) {
                int k = 4 * c4 + t;
                ull b;
                PACK2(b, vals[t], vals[t]);
                int o = k * 10 + base5;
#pragma unroll
                for (int jp = 0; jp < 5; jp++) {
                    FMA2(accz[jp], sW[o +       jp], b, accz[jp]);
                    FMA2(accr[jp], sW[o + 400 + jp], b, accr[jp]);
                    FMA2(acch[jp], sW[o + 800 + jp], b, acch[jp]);
                }
            }
        }
    }

    // ---- Phase B: h contributions to z, r (Uz, Ur); keep only my 10 h's ----
    float myh[10];
    {
        const float4* hp = reinterpret_cast<const float4*>(g_h + (size_t)u * DIM);
#pragma unroll
        for (int c4 = 0; c4 < 5; c4++) {
            float4 a = hp[c4];
            float vals[4] = { a.x, a.y, a.z, a.w };
#pragma unroll
            for (int t = 0; t < 4; t++) {
                int k = 4 * c4 + t;
                if ((k < 10) == lowhalf) myh[k % 10] = vals[t];
                ull b;
                PACK2(b, vals[t], vals[t]);
                int o = k * 10 + base5;
#pragma unroll
                for (int jp = 0; jp < 5; jp++) {
                    FMA2(accz[jp], sW[o + 200 + jp], b, accz[jp]);
                    FMA2(accr[jp], sW[o + 600 + jp], b, accr[jp]);
                }
            }
        }
    }

    // ---- Phase C: r = sigmoid, qa = r * h (my 10 outputs) ----
    float qa[10];
#pragma unroll
    for (int jp = 0; jp < 5; jp++) {
        float r0, r1;
        UNPACK2(r0, r1, accr[jp]);
        qa[2*jp]     = fsigmoid(r0) * myh[2*jp];
        qa[2*jp + 1] = fsigmoid(r1) * myh[2*jp + 1];
    }

    // exchange q with partner (lane ^ 1); q_lo = outputs 0..9, q_hi = 10..19
    float q_lo[10], q_hi[10];
#pragma unroll
    for (int t = 0; t < 10; t++) {
        float other = __shfl_xor_sync(mask, qa[t], 1);
        q_lo[t] = lowhalf ? qa[t] : other;
        q_hi[t] = lowhalf ? other : qa[t];
    }

    // ---- Phase D: q contributions to candidate (Uh) ----
#pragma unroll
    for (int k = 0; k < DIM; k++) {
        float qk = (k < 10) ? q_lo[k] : q_hi[k - 10];
        ull b;
        PACK2(b, qk, qk);
        int o = k * 10 + base5 + 1000;
#pragma unroll
        for (int jp = 0; jp < 5; jp++)
            FMA2(acch[jp], sW[o + jp], b, acch[jp]);
    }

    // ---- Phase E: gates, blend, store my 10 outputs ----
    float* dstp = out_final ? (out_final + (size_t)u * DIM) : (g_h + (size_t)u * DIM);
    float2* d2 = reinterpret_cast<float2*>(dstp + 10 * half);
#pragma unroll
    for (int jp = 0; jp < 5; jp++) {
        float z0, z1, c0, c1;
        UNPACK2(z0, z1, accz[jp]);
        UNPACK2(c0, c1, acch[jp]);
        float zz0 = fsigmoid(z0), zz1 = fsigmoid(z1);
        float hc0 = ftanh(c0),    hc1 = ftanh(c1);
        d2[jp] = make_float2(hc0 + zz0 * (myh[2*jp]     - hc0),
                             hc1 + zz1 * (myh[2*jp + 1] - hc1));
    }
}

// ---------------------------------------------------------------------------
// launch
// ---------------------------------------------------------------------------
extern "C" void kernel_launch(void* const* d_in, const int* in_sizes, int n_in,
                              void* d_out, int out_size) {
    const float* h_in = nullptr;
    const int*   depth = nullptr;
    const int*   esrc = nullptr;
    const int*   edst = nullptr;
    const float* Ws[6] = {};
    const float* Bs[6] = {};
    int wi = 0, bi = 0, ei = 0;
    for (int i = 0; i < n_in; i++) {
        int s = in_sizes[i];
        if (s == NN * DIM)      h_in  = (const float*)d_in[i];
        else if (s == NN)       depth = (const int*)d_in[i];
        else if (s == EE) {
            if (ei == 0) esrc = (const int*)d_in[i];
            else         edst = (const int*)d_in[i];
            ei++;
        }
        else if (s == DIM * DIM && wi < 6) Ws[wi++] = (const float*)d_in[i];
        else if (s == DIM      && bi < 6)  Bs[bi++] = (const float*)d_in[i];
    }

    WParams p;
    for (int m = 0; m < 6; m++) { p.W[m] = Ws[m]; p.B[m] = Bs[m]; }

    float* out = (float*)d_out;

    const int n4       = NN * DIM / 4;
    const int cb_prep  = (n4 + 255) / 256;
    const int cb_edge4 = (EE / 4 + 255) / 256;
    const int cb_node2 = (2 * NN + 255) / 256;   // 2 threads per node
    const int cb_gath  = (NN + 47) / 48;         // 48 nodes per 256-thread block

    const int4* esrc4 = reinterpret_cast<const int4*>(esrc);
    const int4* edst4 = reinterpret_cast<const int4*>(edst);

    prep_kernel<<<cb_prep, 256>>>(h_in, depth, p);
    hist_kernel<<<cb_edge4, 256>>>(esrc4, edst4);
    scan_kernel<<<NBLK, 256>>>();
    fill_kernel<<<cb_edge4, 256>>>(esrc4, edst4);

    for (int i = 0; i < ITERS; i++) {
        int thr = ITERS - i;   // active: depth <= ITERS - i
        gather_kernel<<<cb_gath, 256>>>(i, thr);
        gru_kernel<<<cb_node2, 256>>>(thr, (i == ITERS - 1) ? out : nullptr);
    }
}

// round 17
// speedup vs baseline: 1.7409x; 1.7409x over previous
#include <cuda_runtime.h>
#include <cstdint>

#define NN    200000
#define DIM   20
#define EE    6400000
#define ITERS 3
#define NBLK  ((NN + 255) / 256)   // 782 scan blocks
#define LIFE_DROP 255

typedef unsigned long long ull;

// Persistent scratch (allocations banned; __device__ globals are the workaround)
__device__ __align__(16) float g_h[(size_t)NN * DIM];
__device__ __align__(16) float g_x[(size_t)NN * DIM];
__device__ unsigned char g_depth8[NN];
// Weight image: [m*200 + k*10 + jp] = (W_m[2jp][k], W_m[2jp+1][k]),
// m in {Wz,Uz,Wr,Ur,Wh,Uh}; biases combined W+U at [1200 + g*10 + jp], g=z,r,h.
__device__ __align__(16) float2 g_stage[1232];
// CSR-by-dst with life classes: A = alive all 3 iters, B = iters 0-1, C = iter 0
__device__ int g_degA[NN];
__device__ int g_degB[NN];
__device__ int g_degC[NN];
__device__ int g_curA[NN];   // atomic cursors during fill
__device__ int g_curB[NN];
__device__ int g_curC[NN];
// per-node packed CSR metadata: {off, endA, endB, offNext}
__device__ __align__(16) int4 g_meta[NN];
// class-sorted active node list [A | B | C] and per-iteration limits
__device__ int g_nodelist[NN];
__device__ int g_lim[3];     // lim[0]=cA+cB+cC, lim[1]=cA+cB, lim[2]=cA
__device__ int g_bsum[1024];
__device__ int g_bsumc[1024];   // packed per-block class counts
__device__ int g_scan_done;
__device__ __align__(4) unsigned char g_elife[EE];
__device__ int g_csr[EE];

// ---------------------------------------------------------------------------
// packed f32x2 helpers
// ---------------------------------------------------------------------------
#define FMA2(d, a, b, c) \
    asm("fma.rn.f32x2 %0, %1, %2, %3;" : "=l"(d) : "l"(a), "l"(b), "l"(c))
#define PACK2(d, lo, hi) \
    asm("mov.b64 %0, {%1, %2};" : "=l"(d) : "f"(lo), "f"(hi))
#define UNPACK2(lo, hi, s) \
    asm("mov.b64 {%0, %1}, %2;" : "=f"(lo), "=f"(hi) : "l"(s))

__device__ __forceinline__ float fsigmoid(float v) {
    return 1.f / (1.f + __expf(-v));
}
__device__ __forceinline__ float ftanh(float x) {
    return fmaf(2.f, 1.f / (1.f + __expf(-2.f * x)), -1.f);
}

// ---------------------------------------------------------------------------
// prep (fused init): copy h, pack depth, zero counters, pack weights/biases
// ---------------------------------------------------------------------------
struct WParams {
    const float* W[6];
    const float* B[6];
};

__global__ void prep_kernel(const float* __restrict__ h_in,
                            const int* __restrict__ depth, WParams p) {
    int i = blockIdx.x * blockDim.x + threadIdx.x;
    const int n4 = NN * DIM / 4;
    if (i == 0) g_scan_done = 0;
    if (i < n4)
        reinterpret_cast<float4*>(g_h)[i] = reinterpret_cast<const float4*>(h_in)[i];
    if (i < NN) {
        g_depth8[i] = (unsigned char)__ldg(depth + i);
        g_degA[i] = 0; g_degB[i] = 0; g_degC[i] = 0;
    }
    if (i < 1200) {
        int m = i / 200, r = i % 200;
        int k = r / 10, jp = r % 10;
        const float* w = p.W[m];
        g_stage[m * 200 + k * 10 + jp] =
            make_float2(w[(2 * jp) * DIM + k], w[(2 * jp + 1) * DIM + k]);
    } else if (i < 1230) {
        int t = i - 1200;
        int g = t / 10, jp = t % 10;
        const float* b0 = p.B[2 * g];
        const float* b1 = p.B[2 * g + 1];
        g_stage[1200 + g * 10 + jp] =
            make_float2(b0[2 * jp] + b1[2 * jp], b0[2 * jp + 1] + b1[2 * jp + 1]);
    } else if (i < 1232) {
        g_stage[i] = make_float2(0.f, 0.f);
    }
}

// zero the output buffer once (inactive rows must be 0 in the final output)
__global__ void zero_out_kernel(float4* __restrict__ out4) {
    int i = blockIdx.x * blockDim.x + threadIdx.x;
    if (i < NN * DIM / 4) out4[i] = make_float4(0.f, 0.f, 0.f, 0.f);
}

// ---------------------------------------------------------------------------
// hist: class histogram via fire-and-forget atomics (REDG), life byte per edge
// ---------------------------------------------------------------------------
__global__ void hist_kernel(const int4* __restrict__ esrc4,
                            const int4* __restrict__ edst4) {
    int t = blockIdx.x * blockDim.x + threadIdx.x;
    if (t >= EE / 4) return;
    int4 s4 = __ldg(esrc4 + t);
    int4 d4 = __ldg(edst4 + t);
    int ss[4] = { s4.x, s4.y, s4.z, s4.w };
    int dd[4] = { d4.x, d4.y, d4.z, d4.w };
    unsigned char lf[4];
#pragma unroll
    for (int k = 0; k < 4; k++) {
        int maxd = max((int)g_depth8[ss[k]], (int)g_depth8[dd[k]]);
        unsigned char life = LIFE_DROP;
        if (maxd <= 3) {
            life = (unsigned char)(3 - maxd);
            if (life >= 2)      atomicAdd(&g_degA[dd[k]], 1);
            else if (life == 1) atomicAdd(&g_degB[dd[k]], 1);
            else                atomicAdd(&g_degC[dd[k]], 1);
        }
        lf[k] = life;
    }
    reinterpret_cast<uchar4*>(g_elife)[t] = make_uchar4(lf[0], lf[1], lf[2], lf[3]);
}

// ---------------------------------------------------------------------------
// scan: one wave + software grid barrier. Degree scan -> CSR meta/cursors;
// packed class-membership scan -> class-sorted node list + limits.
// ---------------------------------------------------------------------------
__global__ void __launch_bounds__(256) scan_kernel() {
    __shared__ int sm[256];
    __shared__ ull smu[256];
    int b = blockIdx.x;
    int i = b * 256 + threadIdx.x;

    int d8 = (i < NN) ? (int)g_depth8[i] : 255;
    int a = 0, bb = 0, c = 0;
    if (i < NN) { a = g_degA[i]; bb = g_degB[i]; c = g_degC[i]; }
    int v = a + bb + c;
    int isA = (d8 <= 1) ? 1 : 0;
    int isB = (d8 == 2) ? 1 : 0;
    int isC = (d8 == 3) ? 1 : 0;
    int pk = (isA << 20) | (isB << 10) | isC;

    // degree scan
    sm[threadIdx.x] = v;
    __syncthreads();
    for (int off = 1; off < 256; off <<= 1) {
        int add = (threadIdx.x >= off) ? sm[threadIdx.x - off] : 0;
        __syncthreads();
        sm[threadIdx.x] += add;
        __syncthreads();
    }
    int incl = sm[threadIdx.x];
    int btot = sm[255];

    // packed class scan (fields max 256 < 1024: no cross-field carry)
    __syncthreads();
    sm[threadIdx.x] = pk;
    __syncthreads();
    for (int off = 1; off < 256; off <<= 1) {
        int add = (threadIdx.x >= off) ? sm[threadIdx.x - off] : 0;
        __syncthreads();
        sm[threadIdx.x] += add;
        __syncthreads();
    }
    int inclc = sm[threadIdx.x];
    int ctot = sm[255];

    if (threadIdx.x == 0) {
        g_bsum[b]  = btot;
        g_bsumc[b] = ctot;
        __threadfence();
        atomicAdd(&g_scan_done, 1);
        while (atomicAdd(&g_scan_done, 0) < (int)gridDim.x) { }
    }
    __syncthreads();

    // degree base (prefix over blocks)
    int part = 0;
    for (int t = threadIdx.x; t < b; t += 256) part += g_bsum[t];
    sm[threadIdx.x] = part;
    __syncthreads();
    for (int off = 128; off > 0; off >>= 1) {
        if (threadIdx.x < off) sm[threadIdx.x] += sm[threadIdx.x + off];
        __syncthreads();
    }
    int degbase = sm[0];

    // class prefix + totals (21-bit fields in a ull: A | B<<21 | C<<42)
    ull pre = 0, tot = 0;
    for (int t = threadIdx.x; t < NBLK; t += 256) {
        int pc = g_bsumc[t];
        ull trip = (ull)((pc >> 20) & 1023)
                 | ((ull)((pc >> 10) & 1023) << 21)
                 | ((ull)(pc & 1023) << 42);
        tot += trip;
        if (t < b) pre += trip;
    }
    __syncthreads();
    smu[threadIdx.x] = pre;
    __syncthreads();
    for (int off = 128; off > 0; off >>= 1) {
        if (threadIdx.x < off) smu[threadIdx.x] += smu[threadIdx.x + off];
        __syncthreads();
    }
    ull preS = smu[0];
    __syncthreads();
    smu[threadIdx.x] = tot;
    __syncthreads();
    for (int off = 128; off > 0; off >>= 1) {
        if (threadIdx.x < off) smu[threadIdx.x] += smu[threadIdx.x + off];
        __syncthreads();
    }
    ull totS = smu[0];

    int cApre = (int)(preS & 0x1FFFFF);
    int cBpre = (int)((preS >> 21) & 0x1FFFFF);
    int cCpre = (int)((preS >> 42) & 0x1FFFFF);
    int cAtot = (int)(totS & 0x1FFFFF);
    int cBtot = (int)((totS >> 21) & 0x1FFFFF);
    int cCtot = (int)((totS >> 42) & 0x1FFFFF);

    if (i < NN) {
        int pos = degbase + incl - v;
        g_meta[i] = make_int4(pos, pos + a, pos + a + bb, pos + v);
        g_curA[i] = pos;
        g_curB[i] = pos + a;
        g_curC[i] = pos + a + bb;

        // node-list slot (class-sorted: A | B | C)
        if (isA) {
            int rank = ((inclc >> 20) & 1023) - 1;
            g_nodelist[cApre + rank] = i;
        } else if (isB) {
            int rank = ((inclc >> 10) & 1023) - 1;
            g_nodelist[cAtot + cBpre + rank] = i;
        } else if (isC) {
            int rank = (inclc & 1023) - 1;
            g_nodelist[cAtot + cBtot + cCpre + rank] = i;
        }
    }
    if (b == 0 && threadIdx.x == 0) {
        g_lim[0] = cAtot + cBtot + cCtot;
        g_lim[1] = cAtot + cBtot;
        g_lim[2] = cAtot;
    }
}

// ---------------------------------------------------------------------------
// fill: class-ordered CSR fill via atomic cursors (R13/R15 proven path)
// ---------------------------------------------------------------------------
__global__ void fill_kernel(const int4* __restrict__ esrc4,
                            const int4* __restrict__ edst4) {
    int t = blockIdx.x * blockDim.x + threadIdx.x;
    if (t >= EE / 4) return;
    uchar4 l4 = reinterpret_cast<const uchar4*>(g_elife)[t];
    unsigned char lf[4] = { l4.x, l4.y, l4.z, l4.w };
    int4 s4 = __ldg(esrc4 + t);
    int4 d4 = __ldg(edst4 + t);
    int ss[4] = { s4.x, s4.y, s4.z, s4.w };
    int dd[4] = { d4.x, d4.y, d4.z, d4.w };
#pragma unroll
    for (int k = 0; k < 4; k++) {
        unsigned char life = lf[k];
        if (life == LIFE_DROP) continue;
        int d = dd[k];
        int* cur = (life >= 2) ? &g_curA[d] : (life == 1) ? &g_curB[d] : &g_curC[d];
        int pos = atomicAdd(cur, 1);
        g_csr[pos] = ss[k];
    }
}

// ---------------------------------------------------------------------------
// gather over the active-node list: x[u] = sum h[src] over class prefix
// ---------------------------------------------------------------------------
__global__ void gather_kernel(int iter) {
    int lim = g_lim[iter];
    if (blockIdx.x * 48 >= lim) return;            // fully-idle block
    int lane = threadIdx.x & 31;
    if (lane >= 30) return;                        // 6 groups of 5 per warp
    int warp = (blockIdx.x * blockDim.x + threadIdx.x) >> 5;
    int pos = warp * 6 + lane / 5;
    if (pos >= lim) return;
    int u = g_nodelist[pos];
    int c = lane % 5;

    int4 m = g_meta[u];
    int beg = m.x;
    int end = (iter == 0) ? m.w : (iter == 1) ? m.z : m.y;

    float4 acc = make_float4(0.f, 0.f, 0.f, 0.f);
    int e = beg;
    for (; e + 2 <= end; e += 2) {
        int s0 = g_csr[e];
        int s1 = g_csr[e + 1];
        float4 v0 = __ldg(reinterpret_cast<const float4*>(g_h + (size_t)s0 * DIM) + c);
        float4 v1 = __ldg(reinterpret_cast<const float4*>(g_h + (size_t)s1 * DIM) + c);
        acc.x += v0.x + v1.x; acc.y += v0.y + v1.y;
        acc.z += v0.z + v1.z; acc.w += v0.w + v1.w;
    }
    if (e < end) {
        int s0 = g_csr[e];
        float4 v0 = __ldg(reinterpret_cast<const float4*>(g_h + (size_t)s0 * DIM) + c);
        acc.x += v0.x; acc.y += v0.y; acc.z += v0.z; acc.w += v0.w;
    }
    reinterpret_cast<float4*>(g_x + (size_t)u * DIM)[c] = acc;
}

// ---------------------------------------------------------------------------
// GRU over the active-node list: 2 threads per node, register-diet.
// ---------------------------------------------------------------------------
__global__ void __launch_bounds__(256, 4) gru_kernel(int iter,
                                                     float* __restrict__ out_final) {
    int lim = g_lim[iter];
    if (blockIdx.x * 128 >= lim) return;           // fully-idle block: no staging

    __shared__ __align__(16) ull sW[1232];
    {
        const float4* src = reinterpret_cast<const float4*>(g_stage);
        float4* dst = reinterpret_cast<float4*>(sW);
        for (int t = threadIdx.x; t < 616; t += blockDim.x)
            dst[t] = src[t];
    }
    __syncthreads();

    int gid  = blockIdx.x * blockDim.x + threadIdx.x;
    int pos  = gid >> 1;
    int half = gid & 1;
    bool act = (pos < lim);
    unsigned mask = __ballot_sync(0xFFFFFFFFu, act);
    if (!act) return;

    int u = g_nodelist[pos];
    const int base5 = half * 5;
    const bool lowhalf = (half == 0);

    ull accz[5], accr[5], acch[5];
#pragma unroll
    for (int jp = 0; jp < 5; jp++) {
        accz[jp] = sW[1200 + base5 + jp];
        accr[jp] = sW[1210 + base5 + jp];
        acch[jp] = sW[1220 + base5 + jp];
    }

    // ---- Phase A: x contributions (Wz, Wr, Wh) ----
    {
        const float4* xp = reinterpret_cast<const float4*>(g_x + (size_t)u * DIM);
#pragma unroll
        for (int c4 = 0; c4 < 5; c4++) {
            float4 a = xp[c4];
            float vals[4] = { a.x, a.y, a.z, a.w };
#pragma unroll
            for (int t = 0; t < 4; t++) {
                int k = 4 * c4 + t;
                ull b;
                PACK2(b, vals[t], vals[t]);
                int o = k * 10 + base5;
#pragma unroll
                for (int jp = 0; jp < 5; jp++) {
                    FMA2(accz[jp], sW[o +       jp], b, accz[jp]);
                    FMA2(accr[jp], sW[o + 400 + jp], b, accr[jp]);
                    FMA2(acch[jp], sW[o + 800 + jp], b, acch[jp]);
                }
            }
        }
    }

    // ---- Phase B: h contributions to z, r (Uz, Ur) ----
    float myh[10];
    {
        const float4* hp = reinterpret_cast<const float4*>(g_h + (size_t)u * DIM);
#pragma unroll
        for (int c4 = 0; c4 < 5; c4++) {
            float4 a = hp[c4];
            float vals[4] = { a.x, a.y, a.z, a.w };
#pragma unroll
            for (int t = 0; t < 4; t++) {
                int k = 4 * c4 + t;
                if ((k < 10) == lowhalf) myh[k % 10] = vals[t];
                ull b;
                PACK2(b, vals[t], vals[t]);
                int o = k * 10 + base5;
#pragma unroll
                for (int jp = 0; jp < 5; jp++) {
                    FMA2(accz[jp], sW[o + 200 + jp], b, accz[jp]);
                    FMA2(accr[jp], sW[o + 600 + jp], b, accr[jp]);
                }
            }
        }
    }

    // ---- Phase C: r = sigmoid, qa = r * h ----
    float qa[10];
#pragma unroll
    for (int jp = 0; jp < 5; jp++) {
        float r0, r1;
        UNPACK2(r0, r1, accr[jp]);
        qa[2*jp]     = fsigmoid(r0) * myh[2*jp];
        qa[2*jp + 1] = fsigmoid(r1) * myh[2*jp + 1];
    }

    // exchange q with partner (lane ^ 1)
    float q_lo[10], q_hi[10];
#pragma unroll
    for (int t = 0; t < 10; t++) {
        float other = __shfl_xor_sync(mask, qa[t], 1);
        q_lo[t] = lowhalf ? qa[t] : other;
        q_hi[t] = lowhalf ? other : qa[t];
    }

    // ---- Phase D: q contributions to candidate (Uh) ----
#pragma unroll
    for (int k = 0; k < DIM; k++) {
        float qk = (k < 10) ? q_lo[k] : q_hi[k - 10];
        ull b;
        PACK2(b, qk, qk);
        int o = k * 10 + base5 + 1000;
#pragma unroll
        for (int jp = 0; jp < 5; jp++)
            FMA2(acch[jp], sW[o + jp], b, acch[jp]);
    }

    // ---- Phase E: gates, blend, store ----
    float* dstp = out_final ? (out_final + (size_t)u * DIM) : (g_h + (size_t)u * DIM);
    float2* d2 = reinterpret_cast<float2*>(dstp + 10 * half);
#pragma unroll
    for (int jp = 0; jp < 5; jp++) {
        float z0, z1, c0, c1;
        UNPACK2(z0, z1, accz[jp]);
        UNPACK2(c0, c1, acch[jp]);
        float zz0 = fsigmoid(z0), zz1 = fsigmoid(z1);
        float hc0 = ftanh(c0),    hc1 = ftanh(c1);
        d2[jp] = make_float2(hc0 + zz0 * (myh[2*jp]     - hc0),
                             hc1 + zz1 * (myh[2*jp + 1] - hc1));
    }
}

// ---------------------------------------------------------------------------
// launch
// ---------------------------------------------------------------------------
extern "C" void kernel_launch(void* const* d_in, const int* in_sizes, int n_in,
                              void* d_out, int out_size) {
    const float* h_in = nullptr;
    const int*   depth = nullptr;
    const int*   esrc = nullptr;
    const int*   edst = nullptr;
    const float* Ws[6] = {};
    const float* Bs[6] = {};
    int wi = 0, bi = 0, ei = 0;
    for (int i = 0; i < n_in; i++) {
        int s = in_sizes[i];
        if (s == NN * DIM)      h_in  = (const float*)d_in[i];
        else if (s == NN)       depth = (const int*)d_in[i];
        else if (s == EE) {
            if (ei == 0) esrc = (const int*)d_in[i];
            else         edst = (const int*)d_in[i];
            ei++;
        }
        else if (s == DIM * DIM && wi < 6) Ws[wi++] = (const float*)d_in[i];
        else if (s == DIM      && bi < 6)  Bs[bi++] = (const float*)d_in[i];
    }

    WParams p;
    for (int m = 0; m < 6; m++) { p.W[m] = Ws[m]; p.B[m] = Bs[m]; }

    float* out = (float*)d_out;

    const int n4       = NN * DIM / 4;
    const int cb_prep  = (n4 + 255) / 256;
    const int cb_edge4 = (EE / 4 + 255) / 256;
    const int cb_node2 = (2 * NN + 255) / 256;   // 2 threads per node
    const int cb_gath  = (NN + 47) / 48;         // 48 nodes per 256-thread block

    const int4* esrc4 = reinterpret_cast<const int4*>(esrc);
    const int4* edst4 = reinterpret_cast<const int4*>(edst);

    prep_kernel<<<cb_prep, 256>>>(h_in, depth, p);
    zero_out_kernel<<<cb_prep, 256>>>(reinterpret_cast<float4*>(out));
    hist_kernel<<<cb_edge4, 256>>>(esrc4, edst4);
    scan_kernel<<<NBLK, 256>>>();
    fill_kernel<<<cb_edge4, 256>>>(esrc4, edst4);

    for (int i = 0; i < ITERS; i++) {
        gather_kernel<<<cb_gath, 256>>>(i);
        gru_kernel<<<cb_node2, 256>>>(i, (i == ITERS - 1) ? out : nullptr);
    }
}